// round 4
// baseline (speedup 1.0000x reference)
#include <cuda_runtime.h>
#include <math.h>

#define NN 6144
#define FIN 256
#define FOUT 64
#define ALPHA 0.2f
#define NNZ_MAX (1 << 20)
#define NWORDS (NN / 32)
#define DEGMAX 512

// dynamic SMEM layout for k_fused
#define REP_BYTES (8 * NN)               // 49152: 8 uint8 replicas
#define OFF_SC    (REP_BYTES)            // float s_sc[DEGMAX]
#define OFF_J     (OFF_SC + DEGMAX * 4)  // int   s_j[DEGMAX]
#define OFF_PART  (OFF_J + DEGMAX * 4)   // float s_part[256]
#define OFF_RED   (OFF_PART + 256 * 4)   // float s_red[8]
#define SMEM_BYTES (OFF_RED + 32)

// ---------------- scratch (static device globals; no allocations) ------------
__device__ float  g_h[NN * FOUT];
__device__ float  g_Wh1[NN];
__device__ float  g_Wh2[NN];
__device__ int    g_row_cnt[NN];
__device__ int    g_col_cnt[NN];
__device__ int    g_row_ptr[NN + 1];
__device__ int    g_col_ptr[NN + 1];
__device__ int    g_col_fill[NN];
__device__ int    g_csr_col[NNZ_MAX];
__device__ int    g_csc_row[NNZ_MAX];
__device__ unsigned g_bits[NN * NWORDS];

// ---------------- zero per-launch accumulators -------------------------------
__global__ void k_zero() {
    int t = blockIdx.x * blockDim.x + threadIdx.x;
    if (t < NN) { g_col_cnt[t] = 0; g_col_fill[t] = 0; }
}

// ---------------- pass 1: read adj ONCE -> bitmask + row/col counts ----------
__global__ void k_count(const float* __restrict__ adj) {
    int w = (blockIdx.x * blockDim.x + threadIdx.x) >> 5;
    int lane = threadIdx.x & 31;
    if (w >= NN) return;
    const float* row = adj + (size_t)w * NN;
    unsigned* bits = g_bits + (size_t)w * NWORDS;
    int cnt = 0;
    for (int c0 = 0; c0 < NN; c0 += 32) {
        bool nz = row[c0 + lane] != 0.0f;
        unsigned m = __ballot_sync(0xffffffffu, nz);
        if (lane == 0) bits[c0 >> 5] = m;
        cnt += __popc(m);
        if (nz) atomicAdd(&g_col_cnt[c0 + lane], 1);
    }
    if (lane == 0) g_row_cnt[w] = cnt;
}

// ---------------- exclusive scans (warp-shuffle) -------------------------------
__device__ __forceinline__ void scan6144(const int* __restrict__ in, int* __restrict__ out,
                                         int* s_w) {
    const int tid = threadIdx.x;
    const int lane = tid & 31, warp = tid >> 5;
    const int base = tid * 6;
    int v[6]; int t = 0;
    #pragma unroll
    for (int q = 0; q < 6; q++) { v[q] = t; t += in[base + q]; }
    int inc = t;
    #pragma unroll
    for (int o = 1; o < 32; o <<= 1) {
        int u = __shfl_up_sync(0xffffffffu, inc, o);
        if (lane >= o) inc += u;
    }
    if (lane == 31) s_w[warp] = inc;
    __syncthreads();
    if (warp == 0) {
        int x = s_w[lane];
        int xi = x;
        #pragma unroll
        for (int o = 1; o < 32; o <<= 1) {
            int u = __shfl_up_sync(0xffffffffu, xi, o);
            if (lane >= o) xi += u;
        }
        s_w[lane] = xi - x;
    }
    __syncthreads();
    int off = s_w[warp] + (inc - t);
    #pragma unroll
    for (int q = 0; q < 6; q++) out[base + q] = off + v[q];
    if (tid == 1023) out[NN] = s_w[31] + inc;
}

__global__ void k_scan() {
    __shared__ int s_w[32];
    scan6144(g_row_cnt, g_row_ptr, s_w);
    __syncthreads();
    scan6144(g_col_cnt, g_col_ptr, s_w);
}

// ---------------- pass 2: expand bitmask -> sorted CSR + CSC -----------------
__global__ void k_fill() {
    int w = (blockIdx.x * blockDim.x + threadIdx.x) >> 5;
    int lane = threadIdx.x & 31;
    if (w >= NN) return;
    const unsigned* bits = g_bits + (size_t)w * NWORDS;
    int base = g_row_ptr[w];
    int off = 0;
    #pragma unroll
    for (int it = 0; it < NWORDS / 32; it++) {
        unsigned m = bits[it * 32 + lane];
        int c = __popc(m);
        int pre = c;
        #pragma unroll
        for (int o = 1; o < 32; o <<= 1) {
            int v = __shfl_up_sync(0xffffffffu, pre, o);
            if (lane >= o) pre += v;
        }
        int pos = base + off + (pre - c);
        int col0 = (it * 32 + lane) << 5;
        while (m) {
            int b = __ffs(m) - 1; m &= m - 1;
            int col = col0 + b;
            g_csr_col[pos++] = col;
            int cp = atomicAdd(&g_col_fill[col], 1);
            g_csc_row[g_col_ptr[col] + cp] = w;
        }
        off += __shfl_sync(0xffffffffu, pre, 31);
    }
}

// ---------------- h = x @ W, fused Wh1/Wh2 epilogue ---------------------------
__global__ void k_gemm(const float* __restrict__ x, const float* __restrict__ W,
                       const float* __restrict__ a) {
    __shared__ float xs[4][FIN];
    __shared__ float red1[8], red2[8];
    int tid = threadIdx.x;
    int r0 = blockIdx.x * 4;
    for (int q = tid; q < 4 * FIN; q += 256)
        xs[q >> 8][q & 255] = x[(size_t)(r0 + (q >> 8)) * FIN + (q & 255)];
    __syncthreads();
    int r = tid >> 6, c = tid & 63;
    float acc = 0.f;
    #pragma unroll 8
    for (int k = 0; k < FIN; k++) acc += xs[r][k] * __ldg(&W[k * FOUT + c]);
    g_h[(size_t)(r0 + r) * FOUT + c] = acc;
    float v1 = acc * __ldg(&a[c]);
    float v2 = acc * __ldg(&a[64 + c]);
    int lane = tid & 31, warp = tid >> 5;
    #pragma unroll
    for (int o = 16; o; o >>= 1) {
        v1 += __shfl_down_sync(0xffffffffu, v1, o);
        v2 += __shfl_down_sync(0xffffffffu, v2, o);
    }
    if (lane == 0) { red1[warp] = v1; red2[warp] = v2; }
    __syncthreads();
    if (tid < 4) {
        g_Wh1[r0 + tid] = red1[2 * tid] + red1[2 * tid + 1];
        g_Wh2[r0 + tid] = red2[2 * tid] + red2[2 * tid + 1];
    }
}

// ---------------- fused: adj2 (atomic-free) + adj3 + softmax + SpMM + elu ----
__global__ void k_fused(const float* __restrict__ Wsi, const float* __restrict__ Wei,
                        float* __restrict__ out) {
    extern __shared__ unsigned char smem[];
    unsigned char* rep  = smem;                          // 8 x uint8[NN] replicas
    float* s_sc   = (float*)(smem + OFF_SC);
    int*   s_j    = (int*)(smem + OFF_J);
    float* s_part = (float*)(smem + OFF_PART);
    float* s_red  = (float*)(smem + OFF_RED);

    int i = blockIdx.x, tid = threadIdx.x;
    int warp = tid >> 5, lane = tid & 31;

    // zero replicas (48 KB)
    uint4* rz = (uint4*)rep;
    for (int q = tid; q < REP_BYTES / 16; q += 256) rz[q] = make_uint4(0, 0, 0, 0);

    int rb = g_row_ptr[i];
    int deg = g_row_ptr[i + 1] - rb;
    for (int e = tid; e < deg; e += 256) s_j[e] = g_csr_col[rb + e];
    __syncthreads();

    // phase 1: adj2 row i, atomic-free (per-warp uint8 replica + match_any dedup)
    {
        unsigned char* my = rep + warp * NN;
        for (int kk = warp; kk < deg; kk += 8) {
            int k = s_j[kk];
            int kb = g_row_ptr[k], ke = g_row_ptr[k + 1];
            for (int t0 = kb; t0 < ke; t0 += 32) {
                int t = t0 + lane;
                bool v = t < ke;
                int col = v ? g_csr_col[t] : (NN + lane);   // unique dummies
                unsigned grp = __match_any_sync(0xffffffffu, col);
                bool leader = ((int)(__ffs(grp) - 1) == lane);
                if (v && leader)
                    my[col] = (unsigned char)(my[col] + __popc(grp));
            }
        }
    }
    __syncthreads();

    // phase 1.5: reduce 8 replicas into replica 0 (packed-byte adds, no carries)
    for (int g = tid; g < NN / 16; g += 256) {
        uint4 acc = ((uint4*)rep)[g];
        #pragma unroll
        for (int r = 1; r < 8; r++) {
            uint4 v = ((uint4*)(rep + r * NN))[g];
            acc.x += v.x; acc.y += v.y; acc.z += v.z; acc.w += v.w;
        }
        ((uint4*)rep)[g] = acc;
    }
    __syncthreads();
    const unsigned char* cnt = rep;   // final adj2 row i

    // phase 2: per-edge score; adj3[i,j] = sum over in-nbrs k of j of cnt[k]
    float aWei = fabsf(*Wei), aWsi = fabsf(*Wsi);
    float wh1 = g_Wh1[i];
    for (int e = warp; e < deg; e += 8) {
        int j = s_j[e];
        int cb = g_col_ptr[j], ce = g_col_ptr[j + 1];
        unsigned s3 = 0;
        for (int t = cb + lane; t < ce; t += 32) s3 += (unsigned)cnt[g_csc_row[t]];
        #pragma unroll
        for (int o = 16; o; o >>= 1) s3 += __shfl_down_sync(0xffffffffu, s3, o);
        if (lane == 0) {
            float aw = 1.0f + (float)cnt[j] + (float)s3;
            float wh = wh1 + g_Wh2[j];
            float lr = wh > 0.f ? wh : ALPHA * wh;
            s_sc[e] = aWei * lr + aWsi * aw;
        }
    }
    __syncthreads();

    // phase 3: softmax over neighbors
    float m = -3.4e38f;
    for (int e = tid; e < deg; e += 256) m = fmaxf(m, s_sc[e]);
    #pragma unroll
    for (int o = 16; o; o >>= 1) m = fmaxf(m, __shfl_xor_sync(0xffffffffu, m, o));
    if (lane == 0) s_red[warp] = m;
    __syncthreads();
    m = s_red[lane & 7];
    #pragma unroll
    for (int o = 4; o; o >>= 1) m = fmaxf(m, __shfl_xor_sync(0xffffffffu, m, o));
    m = __shfl_sync(0xffffffffu, m, 0);
    __syncthreads();

    float sum = 0.f;
    for (int e = tid; e < deg; e += 256) { float p = expf(s_sc[e] - m); s_sc[e] = p; sum += p; }
    #pragma unroll
    for (int o = 16; o; o >>= 1) sum += __shfl_xor_sync(0xffffffffu, sum, o);
    if (lane == 0) s_red[warp] = sum;
    __syncthreads();
    sum = s_red[lane & 7];
    #pragma unroll
    for (int o = 4; o; o >>= 1) sum += __shfl_xor_sync(0xffffffffu, sum, o);
    float inv = 1.0f / __shfl_sync(0xffffffffu, sum, 0);
    __syncthreads();

    // phase 4: h_prime[i] = sum_e p_e * h[j_e]  (fp32 gather + accumulate)
    int f = tid & 63, g = tid >> 6;
    float acc = 0.f;
    if (deg > 0) {
        for (int e = g; e < deg; e += 4)
            acc += s_sc[e] * g_h[(size_t)s_j[e] * FOUT + f];
        acc *= inv;
    } else {
        for (int j = g; j < NN; j += 4) acc += g_h[(size_t)j * FOUT + f];
        acc *= (1.0f / NN);
    }
    s_part[tid] = acc; __syncthreads();
    if (tid < 64) {
        float tot = s_part[tid] + s_part[64 + tid] + s_part[128 + tid] + s_part[192 + tid];
        out[(size_t)i * FOUT + tid] = tot > 0.f ? tot : expm1f(tot);
    }
}

// ---------------- launch ------------------------------------------------------
extern "C" void kernel_launch(void* const* d_in, const int* in_sizes, int n_in,
                              void* d_out, int out_size) {
    const float* x   = (const float*)d_in[0];
    const float* adj = (const float*)d_in[1];
    const float* W   = (const float*)d_in[2];
    const float* a   = (const float*)d_in[3];
    const float* Wsi = (const float*)d_in[4];
    const float* Wei = (const float*)d_in[5];
    float* out = (float*)d_out;

    cudaFuncSetAttribute(k_fused, cudaFuncAttributeMaxDynamicSharedMemorySize, SMEM_BYTES);

    k_zero <<<(NN + 255) / 256, 256>>>();
    k_count<<<NN / 8, 256>>>(adj);
    k_gemm <<<NN / 4, 256>>>(x, W, a);
    k_scan <<<1, 1024>>>();
    k_fill <<<NN / 8, 256>>>();
    k_fused<<<NN, 256, SMEM_BYTES>>>(Wsi, Wei, out);
}

// round 5
// speedup vs baseline: 1.9258x; 1.9258x over previous
#include <cuda_runtime.h>
#include <math.h>

#define NN 6144
#define FIN 256
#define FOUT 64
#define ALPHA 0.2f
#define NNZ_MAX (1 << 20)
#define NWORDS (NN / 32)
#define DEGMAX 512

// ---------------- scratch (static device globals; zero-initialized) ----------
__device__ float  g_h[NN * FOUT];
__device__ float  g_Wh1[NN];
__device__ float  g_Wh2[NN];
__device__ int    g_row_cnt[NN];
__device__ int    g_col_cnt[NN];     // zeroed by k_fused epilogue for next call
__device__ int    g_row_ptr[NN + 1];
__device__ int    g_col_ptr[NN + 1];
__device__ int    g_col_fill[NN];    // zeroed by k_fused epilogue for next call
__device__ int    g_csr_col[NNZ_MAX];
__device__ int    g_csc_row[NNZ_MAX];
__device__ unsigned g_bits[NN * NWORDS];

// ---------------- pass 1: read adj ONCE -> bitmask + row/col counts ----------
__global__ void k_count(const float* __restrict__ adj) {
    int w = (blockIdx.x * blockDim.x + threadIdx.x) >> 5;
    int lane = threadIdx.x & 31;
    if (w >= NN) return;
    const float* row = adj + (size_t)w * NN;
    unsigned* bits = g_bits + (size_t)w * NWORDS;
    int cnt = 0;
    for (int c0 = 0; c0 < NN; c0 += 32) {
        bool nz = row[c0 + lane] != 0.0f;
        unsigned m = __ballot_sync(0xffffffffu, nz);
        if (lane == 0) bits[c0 >> 5] = m;
        cnt += __popc(m);
        if (nz) atomicAdd(&g_col_cnt[c0 + lane], 1);
    }
    if (lane == 0) g_row_cnt[w] = cnt;
}

// ---------------- warp-shuffle exclusive scan over 6144 ints -----------------
__device__ __forceinline__ void scan6144(const int* __restrict__ in, int* __restrict__ out,
                                         int* s_w) {
    const int tid = threadIdx.x;          // 1024 threads
    const int lane = tid & 31, warp = tid >> 5;
    const int base = tid * 6;
    int v[6]; int t = 0;
    #pragma unroll
    for (int q = 0; q < 6; q++) { v[q] = t; t += in[base + q]; }
    int inc = t;
    #pragma unroll
    for (int o = 1; o < 32; o <<= 1) {
        int u = __shfl_up_sync(0xffffffffu, inc, o);
        if (lane >= o) inc += u;
    }
    if (lane == 31) s_w[warp] = inc;
    __syncthreads();
    if (warp == 0) {
        int x = s_w[lane];
        int xi = x;
        #pragma unroll
        for (int o = 1; o < 32; o <<= 1) {
            int u = __shfl_up_sync(0xffffffffu, xi, o);
            if (lane >= o) xi += u;
        }
        s_w[lane] = xi - x;
    }
    __syncthreads();
    int off = s_w[warp] + (inc - t);
    #pragma unroll
    for (int q = 0; q < 6; q++) out[base + q] = off + v[q];
    if (tid == 1023) out[NN] = s_w[31] + inc;
}

// ---------------- merged: block 0 = scans, blocks 1..384 = x@W GEMM ----------
__global__ void k_scan_gemm(const float* __restrict__ x, const float* __restrict__ W,
                            const float* __restrict__ a) {
    if (blockIdx.x == 0) {
        __shared__ int s_w[32];
        scan6144(g_row_cnt, g_row_ptr, s_w);
        __syncthreads();
        scan6144(g_col_cnt, g_col_ptr, s_w);
        return;
    }
    __shared__ float xs[16][FIN];         // 16 KB
    __shared__ float red1[32], red2[32];
    int tid = threadIdx.x;                // 1024 threads, 16 rows per block
    int r0 = (blockIdx.x - 1) * 16;
    for (int q = tid; q < 16 * FIN; q += 1024)
        xs[q >> 8][q & 255] = x[(size_t)(r0 + (q >> 8)) * FIN + (q & 255)];
    __syncthreads();
    int r = tid >> 6, c = tid & 63;
    float acc = 0.f;
    #pragma unroll 8
    for (int k = 0; k < FIN; k++) acc += xs[r][k] * __ldg(&W[k * FOUT + c]);
    g_h[(size_t)(r0 + r) * FOUT + c] = acc;
    // epilogue: Wh1 = h . a[:64], Wh2 = h . a[64:]
    float v1 = acc * __ldg(&a[c]);
    float v2 = acc * __ldg(&a[64 + c]);
    int lane = tid & 31, warp = tid >> 5;
    #pragma unroll
    for (int o = 16; o; o >>= 1) {
        v1 += __shfl_down_sync(0xffffffffu, v1, o);
        v2 += __shfl_down_sync(0xffffffffu, v2, o);
    }
    if (lane == 0) { red1[warp] = v1; red2[warp] = v2; }
    __syncthreads();
    if (tid < 16) {
        g_Wh1[r0 + tid] = red1[2 * tid] + red1[2 * tid + 1];
        g_Wh2[r0 + tid] = red2[2 * tid] + red2[2 * tid + 1];
    }
}

// ---------------- pass 2: expand bitmask -> sorted CSR + CSC -----------------
__global__ void k_fill() {
    int w = (blockIdx.x * blockDim.x + threadIdx.x) >> 5;
    int lane = threadIdx.x & 31;
    if (w >= NN) return;
    const unsigned* bits = g_bits + (size_t)w * NWORDS;
    int base = g_row_ptr[w];
    int off = 0;
    #pragma unroll
    for (int it = 0; it < NWORDS / 32; it++) {
        unsigned m = bits[it * 32 + lane];
        int c = __popc(m);
        int pre = c;
        #pragma unroll
        for (int o = 1; o < 32; o <<= 1) {
            int v = __shfl_up_sync(0xffffffffu, pre, o);
            if (lane >= o) pre += v;
        }
        int pos = base + off + (pre - c);
        int col0 = (it * 32 + lane) << 5;
        while (m) {
            int b = __ffs(m) - 1; m &= m - 1;
            int col = col0 + b;
            g_csr_col[pos++] = col;                  // sorted, deterministic
            int cp = atomicAdd(&g_col_fill[col], 1);
            g_csc_row[g_col_ptr[col] + cp] = w;      // unsorted; integer sums only
        }
        off += __shfl_sync(0xffffffffu, pre, 31);
    }
}

// ---------------- fused: adj2 row + adj3@edges + softmax + SpMM + elu --------
__global__ void k_fused(const float* __restrict__ Wsi, const float* __restrict__ Wei,
                        float* __restrict__ out) {
    __shared__ unsigned cnt[NN];          // 24 KB: adj2 row i (exact small ints)
    __shared__ float s_sc[DEGMAX];
    __shared__ int   s_j[DEGMAX];
    __shared__ float s_red[8];
    __shared__ float s_part[256];

    int i = blockIdx.x, tid = threadIdx.x;
    int warp = tid >> 5, lane = tid & 31;

    // reset accumulators for the NEXT kernel_launch call (nothing here reads them)
    if (i < 24) {
        int t = i * 256 + tid;
        g_col_cnt[t] = 0;
        g_col_fill[t] = 0;
    }

    uint4* cz = (uint4*)cnt;
    for (int q = tid; q < NN / 4; q += 256) cz[q] = make_uint4(0, 0, 0, 0);

    int rb = g_row_ptr[i];
    int deg = g_row_ptr[i + 1] - rb;
    for (int e = tid; e < deg; e += 256) s_j[e] = g_csr_col[rb + e];
    __syncthreads();

    // phase 1: adj2 row i (cnt[j] = #paths i->k->j), warp per neighbor k
    for (int kk = warp; kk < deg; kk += 8) {
        int k = s_j[kk];
        int kb = g_row_ptr[k], ke = g_row_ptr[k + 1];
        for (int t = kb + lane; t < ke; t += 32)
            atomicAdd(&cnt[g_csr_col[t]], 1u);
    }
    __syncthreads();

    // phase 2: per-edge score; adj3[i,j] = sum over in-nbrs k of j of cnt[k]
    float aWei = fabsf(*Wei), aWsi = fabsf(*Wsi);
    float wh1 = g_Wh1[i];
    for (int e = warp; e < deg; e += 8) {
        int j = s_j[e];
        int cb = g_col_ptr[j], ce = g_col_ptr[j + 1];
        unsigned s3 = 0;
        for (int t = cb + lane; t < ce; t += 32) s3 += cnt[g_csc_row[t]];
        #pragma unroll
        for (int o = 16; o; o >>= 1) s3 += __shfl_down_sync(0xffffffffu, s3, o);
        if (lane == 0) {
            float aw = 1.0f + (float)cnt[j] + (float)s3;
            float wh = wh1 + g_Wh2[j];
            float lr = wh > 0.f ? wh : ALPHA * wh;
            s_sc[e] = aWei * lr + aWsi * aw;
        }
    }
    __syncthreads();

    // phase 3: softmax over neighbors
    float m = -3.4e38f;
    for (int e = tid; e < deg; e += 256) m = fmaxf(m, s_sc[e]);
    #pragma unroll
    for (int o = 16; o; o >>= 1) m = fmaxf(m, __shfl_xor_sync(0xffffffffu, m, o));
    if (lane == 0) s_red[warp] = m;
    __syncthreads();
    m = s_red[lane & 7];
    #pragma unroll
    for (int o = 4; o; o >>= 1) m = fmaxf(m, __shfl_xor_sync(0xffffffffu, m, o));
    m = __shfl_sync(0xffffffffu, m, 0);
    __syncthreads();

    float sum = 0.f;
    for (int e = tid; e < deg; e += 256) { float p = expf(s_sc[e] - m); s_sc[e] = p; sum += p; }
    #pragma unroll
    for (int o = 16; o; o >>= 1) sum += __shfl_xor_sync(0xffffffffu, sum, o);
    if (lane == 0) s_red[warp] = sum;
    __syncthreads();
    sum = s_red[lane & 7];
    #pragma unroll
    for (int o = 4; o; o >>= 1) sum += __shfl_xor_sync(0xffffffffu, sum, o);
    float inv = 1.0f / __shfl_sync(0xffffffffu, sum, 0);
    __syncthreads();

    // phase 4: h_prime[i] = sum_e p_e * h[j_e]  (fp32 gather + accumulate)
    int f = tid & 63, g = tid >> 6;
    float acc = 0.f;
    if (deg > 0) {
        for (int e = g; e < deg; e += 4)
            acc += s_sc[e] * g_h[(size_t)s_j[e] * FOUT + f];
        acc *= inv;
    } else {
        for (int j = g; j < NN; j += 4) acc += g_h[(size_t)j * FOUT + f];
        acc *= (1.0f / NN);
    }
    s_part[tid] = acc; __syncthreads();
    if (tid < 64) {
        float tot = s_part[tid] + s_part[64 + tid] + s_part[128 + tid] + s_part[192 + tid];
        out[(size_t)i * FOUT + tid] = tot > 0.f ? tot : expm1f(tot);
    }
}

// ---------------- launch: 4 kernels, k_fused at launch index 3 ----------------
extern "C" void kernel_launch(void* const* d_in, const int* in_sizes, int n_in,
                              void* d_out, int out_size) {
    const float* x   = (const float*)d_in[0];
    const float* adj = (const float*)d_in[1];
    const float* W   = (const float*)d_in[2];
    const float* a   = (const float*)d_in[3];
    const float* Wsi = (const float*)d_in[4];
    const float* Wei = (const float*)d_in[5];
    float* out = (float*)d_out;

    k_count    <<<NN / 8, 256>>>(adj);
    k_scan_gemm<<<1 + NN / 16, 1024>>>(x, W, a);
    k_fill     <<<NN / 8, 256>>>();
    k_fused    <<<NN, 256>>>(Wsi, Wei, out);
}